// round 16
// baseline (speedup 1.0000x reference)
#include <cuda_runtime.h>
#include <cuda_fp16.h>
#include <cstdint>
#include <cstddef>

typedef unsigned long long ull;

#define TSTEPS 1024
#define GDIM   1024
#define HSEQ   ((size_t)TSTEPS * 256 * 256)

__device__ float g_xpb[(size_t)TSTEPS * 256 * GDIM];   // x@W_ih + bias
__device__ int   g_ready[TSTEPS];                       // per-timestep proj counters

__device__ __forceinline__ uint32_t packh2(float lo, float hi) {
    uint32_t u;
    asm("cvt.rn.f16x2.f32 %0, %1, %2;" : "=r"(u) : "f"(hi), "f"(lo));
    return u;
}
__device__ __forceinline__ uint32_t sptr(const void* p) {
    return (uint32_t)__cvta_generic_to_shared(p);
}
__device__ __forceinline__ void ldsm4(uint32_t a[4], uint32_t addr) {
    asm volatile("ldmatrix.sync.aligned.m8n8.x4.shared.b16 {%0,%1,%2,%3}, [%4];"
        : "=r"(a[0]), "=r"(a[1]), "=r"(a[2]), "=r"(a[3]) : "r"(addr));
}
__device__ __forceinline__ void mma_tf32(float c[4], const uint32_t a[4], uint32_t b0, uint32_t b1) {
    asm volatile("mma.sync.aligned.m16n8k8.row.col.f32.tf32.tf32.f32 "
        "{%0,%1,%2,%3}, {%4,%5,%6,%7}, {%8,%9}, {%0,%1,%2,%3};"
        : "+f"(c[0]), "+f"(c[1]), "+f"(c[2]), "+f"(c[3])
        : "r"(a[0]), "r"(a[1]), "r"(a[2]), "r"(a[3]), "r"(b0), "r"(b1));
}
__device__ __forceinline__ void mma_f16(float c[4], const uint32_t a[4], uint32_t b0, uint32_t b1) {
    asm volatile("mma.sync.aligned.m16n8k16.row.col.f32.f16.f16.f32 "
        "{%0,%1,%2,%3}, {%4,%5,%6,%7}, {%8,%9}, {%0,%1,%2,%3};"
        : "+f"(c[0]), "+f"(c[1]), "+f"(c[2]), "+f"(c[3])
        : "r"(a[0]), "r"(a[1]), "r"(a[2]), "r"(a[3]), "r"(b0), "r"(b1));
}
__device__ __forceinline__ float sigf(float x) { return 1.f / (1.f + __expf(-x)); }
__device__ __forceinline__ uint32_t mapa_rank(uint32_t addr, uint32_t rank) {
    uint32_t r;
    asm("mapa.shared::cluster.u32 %0, %1, %2;" : "=r"(r) : "r"(addr), "r"(rank));
    return r;
}
__device__ __forceinline__ void mbar_init(uint32_t a, uint32_t cnt) {
    asm volatile("mbarrier.init.shared.b64 [%0], %1;" :: "r"(a), "r"(cnt) : "memory");
}
__device__ __forceinline__ void mbar_expect(uint32_t a, uint32_t bytes) {
    asm volatile("mbarrier.arrive.expect_tx.shared.b64 _, [%0], %1;" :: "r"(a), "r"(bytes) : "memory");
}
__device__ __forceinline__ void mbar_wait(uint32_t a, uint32_t parity) {
    asm volatile(
        "{\n\t.reg .pred P;\n\t"
        "WL_%=:\n\t"
        "mbarrier.try_wait.parity.acquire.cta.shared::cta.b64 P, [%0], %1, 0x989680;\n\t"
        "@P bra.uni WD_%=;\n\t"
        "bra.uni WL_%=;\n\t"
        "WD_%=:\n\t}"
        :: "r"(a), "r"(parity) : "memory");
}
__device__ __forceinline__ void bulk_s2s(uint32_t dst, uint32_t src, uint32_t bytes, uint32_t mbar) {
    asm volatile("cp.async.bulk.shared::cluster.shared::cta.mbarrier::complete_tx::bytes "
                 "[%0], [%1], %2, [%3];"
        :: "r"(dst), "r"(src), "r"(bytes), "r"(mbar) : "memory");
}
__device__ __forceinline__ void bar_sync(int id, int cnt) {
    asm volatile("bar.sync %0, %1;" :: "r"(id), "r"(cnt) : "memory");
}
__device__ __forceinline__ void cpa16(uint32_t dst, const float* src) {
    asm volatile("cp.async.cg.shared.global [%0], [%1], 16;" :: "r"(dst), "l"(src) : "memory");
}
__device__ __forceinline__ void wait_ready(int t) {
    int v;
    do {
        asm volatile("ld.acquire.gpu.global.b32 %0, [%1];"
                     : "=r"(v) : "l"(g_ready + t) : "memory");
    } while (v < 16);
}

// layout constants
#define ASTR 36
#define BSTR 136
#define BUF_FLOATS (128 * ASTR + 32 * BSTR)        // 8960 floats = 35840 B
#define NBUF 4
#define PROJ_SMEM  (NBUF * BUF_FLOATS * 4)         // 143360 bytes

#define AS_B(gi,b)  (((gi)*2+(b))*8192)
#define ST_B(gi)    (32768 + (gi)*1024)
#define MB_B        34816

__global__ void reset_kernel() { g_ready[threadIdx.x] = 0; }

// ============================================================================
// FUSED kernel: blocks 0..63 = lstm (8 clusters x 8 CTAs, R14 recurrence);
// blocks 64.. = proj producer CTAs (16 per timestep, bid-ordered) with a
// 4-buffer / stage-2-ahead cp.async pipeline (hides chunk latency at 1 CTA/SM).
// ============================================================================
__global__ void __launch_bounds__(256, 1) __cluster_dims__(8, 1, 1)
fused_kernel(const float* __restrict__ X, const float* __restrict__ Wih,
             const float* __restrict__ bias, const float* __restrict__ Whh,
             float* __restrict__ out, int tail) {
    extern __shared__ char smc[];

    if (blockIdx.x >= 64) {
        // ===================== PROJ role =====================
        float* sm = (float*)smc;
        const int pid = blockIdx.x - 64;
        const int tid = threadIdx.x;
        const int nb = (pid & 7) * 128;
        const int my = pid >> 3;
        const int mb = my * 128;
        const int w = tid >> 5, lane = tid & 31;
        const int g = lane >> 2, t4 = lane & 3;
        const int mw = w & 1, nw = w >> 1;

        const int a_r = tid >> 3, a_c4 = tid & 7;
        const int b_r = tid >> 5, b_c4 = tid & 31;

        float acc[4][4][4] = {};
        const uint32_t abyte = (uint32_t)((mw * 64 + (lane & 15)) * ASTR * 4 + (lane >> 4) * 16);

        auto stage = [&](int kc) {
            float* As = sm + (kc & 3) * BUF_FLOATS;
            float* Bs = As + 128 * ASTR;
            #pragma unroll
            for (int i = 0; i < 4; i++) {
                int r = a_r + 32 * i;
                cpa16(sptr(As + r * ASTR + a_c4 * 4),
                      X + (size_t)(mb + r) * 256 + kc * 32 + a_c4 * 4);
            }
            #pragma unroll
            for (int i = 0; i < 4; i++) {
                int r = b_r + 8 * i;
                cpa16(sptr(Bs + r * BSTR + b_c4 * 4),
                      Wih + (size_t)(kc * 32 + r) * GDIM + nb + b_c4 * 4);
            }
            asm volatile("cp.async.commit_group;" ::: "memory");
        };

        stage(0);
        stage(1);
        #pragma unroll 1
        for (int kc = 0; kc < 8; kc++) {
            if (kc + 2 < 8) stage(kc + 2);
            if (kc < 6)      asm volatile("cp.async.wait_group 2;" ::: "memory");
            else if (kc == 6) asm volatile("cp.async.wait_group 1;" ::: "memory");
            else              asm volatile("cp.async.wait_group 0;" ::: "memory");
            __syncthreads();
            float* As = sm + (kc & 3) * BUF_FLOATS;
            float* Bs = As + 128 * ASTR;
            const uint32_t abase = sptr(As) + abyte;
            #pragma unroll
            for (int kt = 0; kt < 4; kt++) {
                uint32_t af[4][4];
                #pragma unroll
                for (int mt = 0; mt < 4; mt++)
                    ldsm4(af[mt], abase + (uint32_t)(mt * 16 * ASTR * 4) + kt * 32);
                #pragma unroll
                for (int nt = 0; nt < 4; nt++) {
                    int col = nw * 32 + nt * 8 + g;
                    uint32_t b0 = __float_as_uint(Bs[(kt * 8 + t4) * BSTR + col]);
                    uint32_t b1 = __float_as_uint(Bs[(kt * 8 + t4 + 4) * BSTR + col]);
                    #pragma unroll
                    for (int mt = 0; mt < 4; mt++) mma_tf32(acc[mt][nt], af[mt], b0, b1);
                }
            }
        }
        #pragma unroll
        for (int mt = 0; mt < 4; mt++) {
            size_t r0 = (size_t)(mb + mw * 64 + mt * 16 + g);
            #pragma unroll
            for (int nt = 0; nt < 4; nt++) {
                int col = nb + nw * 32 + nt * 8 + 2 * t4;
                float b0 = __ldg(bias + col), b1 = __ldg(bias + col + 1);
                *(float2*)(g_xpb + r0 * GDIM + col) =
                    make_float2(acc[mt][nt][0] + b0, acc[mt][nt][1] + b1);
                *(float2*)(g_xpb + (r0 + 8) * GDIM + col) =
                    make_float2(acc[mt][nt][2] + b0, acc[mt][nt][3] + b1);
            }
        }
        __syncthreads();
        __threadfence();
        if (tid == 0) atomicAdd(&g_ready[my >> 1], 1);
        return;
    }

    // ===================== LSTM role (R14 recurrence + ready-poll) =====================
    const uint32_t smem0 = sptr(smc);
    const int tid = threadIdx.x;
    const int w = tid >> 5, lane = tid & 31;
    const int gi = w >> 2;
    const int ww = w & 3;
    const int ltid = tid & 127;
    const int g = lane >> 2, t4 = lane & 3;
    const int cid = blockIdx.x >> 3;
    uint32_t r; asm("mov.u32 %0, %%cluster_ctarank;" : "=r"(r));

    if (tid == 0) {
        #pragma unroll
        for (int i = 0; i < 4; i++) mbar_init(smem0 + MB_B + i * 8, 1);
        #pragma unroll
        for (int i = 0; i < 4; i++) mbar_expect(smem0 + MB_B + i * 8, 8192);
    }

    uint32_t bf[16][4][2];
    #pragma unroll
    for (int kt = 0; kt < 16; kt++)
        #pragma unroll
        for (int nt = 0; nt < 4; nt++) {
            int gcol = nt * 256 + (int)r * 32 + ww * 8 + g;
            bf[kt][nt][0] = packh2(Whh[(size_t)(kt * 16 + 2 * t4) * GDIM + gcol],
                                   Whh[(size_t)(kt * 16 + 2 * t4 + 1) * GDIM + gcol]);
            bf[kt][nt][1] = packh2(Whh[(size_t)(kt * 16 + 8 + 2 * t4) * GDIM + gcol],
                                   Whh[(size_t)(kt * 16 + 8 + 2 * t4 + 1) * GDIM + gcol]);
        }
    __syncthreads();
    asm volatile("barrier.cluster.arrive.aligned;" ::: "memory");
    asm volatile("barrier.cluster.wait.aligned;" ::: "memory");

    const uint32_t laneoff = (uint32_t)((lane >> 4) * 256 + (lane & 15) * 16);
    const int hcol = ww * 8 + 2 * t4;
    const uint32_t st0 = (uint32_t)(ww * 256 + g * 16 + t4 * 4);
    const uint32_t st1 = (uint32_t)(ww * 256 + (g + 8) * 16 + t4 * 4);
    float c00 = 0.f, c01 = 0.f, c10 = 0.f, c11 = 0.f;
    int ph[2] = {0, 0};

    wait_ready(0);

    for (int t = 0; t < TSTEPS; t++) {
        const int b = t & 1, nbuf = b ^ 1;
        const float* xr = g_xpb + (size_t)t * (256 * GDIM)
                        + (size_t)(cid * 32 + gi * 16 + g) * GDIM + (int)r * 32 + hcol;
        const float* xr2 = xr + 8 * GDIM;
        float2 xi0 = __ldcg((const float2*)xr);
        float2 xf0 = __ldcg((const float2*)(xr + 256));
        float2 xg0 = __ldcg((const float2*)(xr + 512));
        float2 xo0 = __ldcg((const float2*)(xr + 768));
        float2 xi1 = __ldcg((const float2*)xr2);
        float2 xf1 = __ldcg((const float2*)(xr2 + 256));
        float2 xg1 = __ldcg((const float2*)(xr2 + 512));
        float2 xo1 = __ldcg((const float2*)(xr2 + 768));

        float acc[4][4] = {}, acc2[4][4] = {};
        if (t) {
            uint32_t mb = smem0 + MB_B + (gi * 2 + b) * 8;
            mbar_wait(mb, (uint32_t)ph[b]);
            ph[b] ^= 1;
            if (ltid == 0) mbar_expect(mb, 8192);
            uint32_t ab = smem0 + (uint32_t)AS_B(gi, b) + laneoff;
            #pragma unroll
            for (int kt = 0; kt < 8; kt++) {
                uint32_t a[4];
                ldsm4(a, ab + (uint32_t)(kt * 512));
                #pragma unroll
                for (int nt = 0; nt < 4; nt++) mma_f16(acc[nt], a, bf[kt][nt][0], bf[kt][nt][1]);
            }
            #pragma unroll
            for (int kt = 8; kt < 16; kt++) {
                uint32_t a[4];
                ldsm4(a, ab + (uint32_t)(kt * 512));
                #pragma unroll
                for (int nt = 0; nt < 4; nt++) mma_f16(acc2[nt], a, bf[kt][nt][0], bf[kt][nt][1]);
            }
        }
        float i00 = sigf(acc[0][0] + acc2[0][0] + xi0.x);
        float i01 = sigf(acc[0][1] + acc2[0][1] + xi0.y);
        float i10 = sigf(acc[0][2] + acc2[0][2] + xi1.x);
        float i11 = sigf(acc[0][3] + acc2[0][3] + xi1.y);
        float f00 = sigf(acc[1][0] + acc2[1][0] + xf0.x);
        float f01 = sigf(acc[1][1] + acc2[1][1] + xf0.y);
        float f10 = sigf(acc[1][2] + acc2[1][2] + xf1.x);
        float f11 = sigf(acc[1][3] + acc2[1][3] + xf1.y);
        float G00 = tanhf(acc[2][0] + acc2[2][0] + xg0.x);
        float G01 = tanhf(acc[2][1] + acc2[2][1] + xg0.y);
        float G10 = tanhf(acc[2][2] + acc2[2][2] + xg1.x);
        float G11 = tanhf(acc[2][3] + acc2[2][3] + xg1.y);
        float o00 = sigf(acc[3][0] + acc2[3][0] + xo0.x);
        float o01 = sigf(acc[3][1] + acc2[3][1] + xo0.y);
        float o10 = sigf(acc[3][2] + acc2[3][2] + xo1.x);
        float o11 = sigf(acc[3][3] + acc2[3][3] + xo1.y);
        c00 = f00 * c00 + i00 * G00;  c01 = f01 * c01 + i01 * G01;
        c10 = f10 * c10 + i10 * G10;  c11 = f11 * c11 + i11 * G11;
        float h00 = o00 * tanhf(c00), h01 = o01 * tanhf(c01);
        float h10 = o10 * tanhf(c10), h11 = o11 * tanhf(c11);
        *(uint32_t*)(smc + ST_B(gi) + st0) = packh2(h00, h01);
        *(uint32_t*)(smc + ST_B(gi) + st1) = packh2(h10, h11);
        bar_sync(1 + gi, 128);
        if (ltid == 0 && t < TSTEPS - 1) {
            asm volatile("fence.proxy.async.shared::cta;" ::: "memory");
            uint32_t src = smem0 + (uint32_t)ST_B(gi);
            uint32_t dstl = smem0 + (uint32_t)AS_B(gi, nbuf) + r * 1024;
            uint32_t mbl = smem0 + MB_B + (gi * 2 + nbuf) * 8;
            #pragma unroll
            for (uint32_t dr = 0; dr < 8; dr++)
                bulk_s2s(mapa_rank(dstl, dr), src, 1024u, mapa_rank(mbl, dr));
        }
        size_t row0 = (size_t)(cid * 32 + gi * 16 + g) * 256 + (int)r * 32 + hcol;
        *(float2*)(out + (size_t)t * 65536 + row0) = make_float2(h00, h01);
        *(float2*)(out + (size_t)t * 65536 + row0 + 8 * 256) = make_float2(h10, h11);
        if (tail && t == TSTEPS - 1) {
            *(float2*)(out + HSEQ + row0) = make_float2(h00, h01);
            *(float2*)(out + HSEQ + row0 + 8 * 256) = make_float2(h10, h11);
            *(float2*)(out + HSEQ + 65536 + row0) = make_float2(c00, c01);
            *(float2*)(out + HSEQ + 65536 + row0 + 8 * 256) = make_float2(c10, c11);
        }
        if (t < TSTEPS - 1) wait_ready(t + 1);
    }
    if (ltid == 0) {
        asm volatile("cp.async.bulk.commit_group;" ::: "memory");
        asm volatile("cp.async.bulk.wait_group.read 0;" ::: "memory");
    }
    __syncthreads();
    asm volatile("barrier.cluster.arrive.aligned;" ::: "memory");
    asm volatile("barrier.cluster.wait.aligned;" ::: "memory");
}

extern "C" void kernel_launch(void* const* d_in, const int* in_sizes, int n_in,
                              void* d_out, int out_size) {
    const float* x    = (const float*)d_in[0];
    const float* wih  = (const float*)d_in[1];
    const float* whh  = (const float*)d_in[2];
    const float* bias = (const float*)d_in[3];
    float* out = (float*)d_out;
    (void)in_sizes; (void)n_in;
    cudaFuncSetAttribute(fused_kernel, cudaFuncAttributeMaxDynamicSharedMemorySize, PROJ_SMEM);
    reset_kernel<<<1, TSTEPS>>>();
    int tail = ((size_t)out_size >= HSEQ + 2 * 65536) ? 1 : 0;
    fused_kernel<<<64 + 16384, 256, PROJ_SMEM>>>(x, wih, bias, whh, out, tail);
}

// round 17
// speedup vs baseline: 1.2033x; 1.2033x over previous
#include <cuda_runtime.h>
#include <cuda_fp16.h>
#include <cstdint>
#include <cstddef>

typedef unsigned long long ull;

#define TSTEPS 1024
#define GDIM   1024
#define HSEQ   ((size_t)TSTEPS * 256 * 256)

__device__ float g_xpb[(size_t)TSTEPS * 256 * GDIM];   // x@W_ih + bias
__device__ int   g_ready[TSTEPS];                       // per-timestep proj counters

__device__ __forceinline__ uint32_t packh2(float lo, float hi) {
    uint32_t u;
    asm("cvt.rn.f16x2.f32 %0, %1, %2;" : "=r"(u) : "f"(hi), "f"(lo));
    return u;
}
__device__ __forceinline__ uint32_t sptr(const void* p) {
    return (uint32_t)__cvta_generic_to_shared(p);
}
__device__ __forceinline__ void ldsm4(uint32_t a[4], uint32_t addr) {
    asm volatile("ldmatrix.sync.aligned.m8n8.x4.shared.b16 {%0,%1,%2,%3}, [%4];"
        : "=r"(a[0]), "=r"(a[1]), "=r"(a[2]), "=r"(a[3]) : "r"(addr));
}
__device__ __forceinline__ void mma_tf32(float c[4], const uint32_t a[4], uint32_t b0, uint32_t b1) {
    asm volatile("mma.sync.aligned.m16n8k8.row.col.f32.tf32.tf32.f32 "
        "{%0,%1,%2,%3}, {%4,%5,%6,%7}, {%8,%9}, {%0,%1,%2,%3};"
        : "+f"(c[0]), "+f"(c[1]), "+f"(c[2]), "+f"(c[3])
        : "r"(a[0]), "r"(a[1]), "r"(a[2]), "r"(a[3]), "r"(b0), "r"(b1));
}
__device__ __forceinline__ void mma_f16(float c[4], const uint32_t a[4], uint32_t b0, uint32_t b1) {
    asm volatile("mma.sync.aligned.m16n8k16.row.col.f32.f16.f16.f32 "
        "{%0,%1,%2,%3}, {%4,%5,%6,%7}, {%8,%9}, {%0,%1,%2,%3};"
        : "+f"(c[0]), "+f"(c[1]), "+f"(c[2]), "+f"(c[3])
        : "r"(a[0]), "r"(a[1]), "r"(a[2]), "r"(a[3]), "r"(b0), "r"(b1));
}
__device__ __forceinline__ float sigf(float x) { return 1.f / (1.f + __expf(-x)); }
__device__ __forceinline__ uint32_t mapa_rank(uint32_t addr, uint32_t rank) {
    uint32_t r;
    asm("mapa.shared::cluster.u32 %0, %1, %2;" : "=r"(r) : "r"(addr), "r"(rank));
    return r;
}
__device__ __forceinline__ void mbar_init(uint32_t a, uint32_t cnt) {
    asm volatile("mbarrier.init.shared.b64 [%0], %1;" :: "r"(a), "r"(cnt) : "memory");
}
__device__ __forceinline__ void mbar_expect(uint32_t a, uint32_t bytes) {
    asm volatile("mbarrier.arrive.expect_tx.shared.b64 _, [%0], %1;" :: "r"(a), "r"(bytes) : "memory");
}
__device__ __forceinline__ void mbar_wait(uint32_t a, uint32_t parity) {
    asm volatile(
        "{\n\t.reg .pred P;\n\t"
        "WL_%=:\n\t"
        "mbarrier.try_wait.parity.acquire.cta.shared::cta.b64 P, [%0], %1, 0x989680;\n\t"
        "@P bra.uni WD_%=;\n\t"
        "bra.uni WL_%=;\n\t"
        "WD_%=:\n\t}"
        :: "r"(a), "r"(parity) : "memory");
}
__device__ __forceinline__ void bulk_s2s(uint32_t dst, uint32_t src, uint32_t bytes, uint32_t mbar) {
    asm volatile("cp.async.bulk.shared::cluster.shared::cta.mbarrier::complete_tx::bytes "
                 "[%0], [%1], %2, [%3];"
        :: "r"(dst), "r"(src), "r"(bytes), "r"(mbar) : "memory");
}
__device__ __forceinline__ void bar_sync(int id, int cnt) {
    asm volatile("bar.sync %0, %1;" :: "r"(id), "r"(cnt) : "memory");
}
__device__ __forceinline__ void cpa16(uint32_t dst, const float* src) {
    asm volatile("cp.async.cg.shared.global [%0], [%1], 16;" :: "r"(dst), "l"(src) : "memory");
}
__device__ __forceinline__ void wait_ready(int t) {
    int v;
    do {
        asm volatile("ld.acquire.gpu.global.b32 %0, [%1];"
                     : "=r"(v) : "l"(g_ready + t) : "memory");
    } while (v < 16);
}

// layout constants
#define ASTR 36
#define BSTR 136
#define BUF_FLOATS (128 * ASTR + 32 * BSTR)        // 8960 floats = 35840 B
#define PROJ_SMEM  (2 * BUF_FLOATS * 4)            // 71680 bytes (R15 2-buffer)

#define AS_B(gi,b)  (((gi)*2+(b))*8192)
#define ST_B(gi)    (32768 + (gi)*1024)
#define MB_B        34816

__global__ void reset_kernel() { g_ready[threadIdx.x] = 0; }

// ============================================================================
// FUSED kernel: blocks 0..63 = lstm (8 clusters x 8 CTAs, R14 recurrence);
// blocks 64.. = proj producer CTAs (16 per timestep, bid-ordered), R15
// 2-buffer cp.async pipeline. Handshake: proj release-increments g_ready[t];
// lstm: ONE poller thread per 128-thread group + named barrier (kills the
// 16K-thread same-address L2 polling storm of R15/R16).
// ============================================================================
__global__ void __launch_bounds__(256, 1) __cluster_dims__(8, 1, 1)
fused_kernel(const float* __restrict__ X, const float* __restrict__ Wih,
             const float* __restrict__ bias, const float* __restrict__ Whh,
             float* __restrict__ out, int tail) {
    extern __shared__ char smc[];

    if (blockIdx.x >= 64) {
        // ===================== PROJ role (R15 version) =====================
        float* sm = (float*)smc;
        const int pid = blockIdx.x - 64;
        const int tid = threadIdx.x;
        const int nb = (pid & 7) * 128;
        const int my = pid >> 3;
        const int mb = my * 128;
        const int w = tid >> 5, lane = tid & 31;
        const int g = lane >> 2, t4 = lane & 3;
        const int mw = w & 1, nw = w >> 1;

        const int a_r = tid >> 3, a_c4 = tid & 7;
        const int b_r = tid >> 5, b_c4 = tid & 31;

        float acc[4][4][4] = {};
        const uint32_t abyte = (uint32_t)((mw * 64 + (lane & 15)) * ASTR * 4 + (lane >> 4) * 16);

        auto stage = [&](int kc, int buf) {
            float* As = sm + buf * BUF_FLOATS;
            float* Bs = As + 128 * ASTR;
            #pragma unroll
            for (int i = 0; i < 4; i++) {
                int r = a_r + 32 * i;
                cpa16(sptr(As + r * ASTR + a_c4 * 4),
                      X + (size_t)(mb + r) * 256 + kc * 32 + a_c4 * 4);
            }
            #pragma unroll
            for (int i = 0; i < 4; i++) {
                int r = b_r + 8 * i;
                cpa16(sptr(Bs + r * BSTR + b_c4 * 4),
                      Wih + (size_t)(kc * 32 + r) * GDIM + nb + b_c4 * 4);
            }
            asm volatile("cp.async.commit_group;" ::: "memory");
        };

        stage(0, 0);
        #pragma unroll 1
        for (int kc = 0; kc < 8; kc++) {
            if (kc < 7) stage(kc + 1, (kc + 1) & 1);
            if (kc < 7) asm volatile("cp.async.wait_group 1;" ::: "memory");
            else        asm volatile("cp.async.wait_group 0;" ::: "memory");
            __syncthreads();
            float* As = sm + (kc & 1) * BUF_FLOATS;
            float* Bs = As + 128 * ASTR;
            const uint32_t abase = sptr(As) + abyte;
            #pragma unroll
            for (int kt = 0; kt < 4; kt++) {
                uint32_t af[4][4];
                #pragma unroll
                for (int mt = 0; mt < 4; mt++)
                    ldsm4(af[mt], abase + (uint32_t)(mt * 16 * ASTR * 4) + kt * 32);
                #pragma unroll
                for (int nt = 0; nt < 4; nt++) {
                    int col = nw * 32 + nt * 8 + g;
                    uint32_t b0 = __float_as_uint(Bs[(kt * 8 + t4) * BSTR + col]);
                    uint32_t b1 = __float_as_uint(Bs[(kt * 8 + t4 + 4) * BSTR + col]);
                    #pragma unroll
                    for (int mt = 0; mt < 4; mt++) mma_tf32(acc[mt][nt], af[mt], b0, b1);
                }
            }
            __syncthreads();
        }
        #pragma unroll
        for (int mt = 0; mt < 4; mt++) {
            size_t r0 = (size_t)(mb + mw * 64 + mt * 16 + g);
            #pragma unroll
            for (int nt = 0; nt < 4; nt++) {
                int col = nb + nw * 32 + nt * 8 + 2 * t4;
                float b0 = __ldg(bias + col), b1 = __ldg(bias + col + 1);
                *(float2*)(g_xpb + r0 * GDIM + col) =
                    make_float2(acc[mt][nt][0] + b0, acc[mt][nt][1] + b1);
                *(float2*)(g_xpb + (r0 + 8) * GDIM + col) =
                    make_float2(acc[mt][nt][2] + b0, acc[mt][nt][3] + b1);
            }
        }
        __syncthreads();
        __threadfence();
        if (tid == 0) atomicAdd(&g_ready[my >> 1], 1);
        return;
    }

    // ===================== LSTM role =====================
    const uint32_t smem0 = sptr(smc);
    const int tid = threadIdx.x;
    const int w = tid >> 5, lane = tid & 31;
    const int gi = w >> 2;
    const int ww = w & 3;
    const int ltid = tid & 127;
    const int g = lane >> 2, t4 = lane & 3;
    const int cid = blockIdx.x >> 3;
    uint32_t r; asm("mov.u32 %0, %%cluster_ctarank;" : "=r"(r));

    if (tid == 0) {
        #pragma unroll
        for (int i = 0; i < 4; i++) mbar_init(smem0 + MB_B + i * 8, 1);
        #pragma unroll
        for (int i = 0; i < 4; i++) mbar_expect(smem0 + MB_B + i * 8, 8192);
    }

    uint32_t bf[16][4][2];
    #pragma unroll
    for (int kt = 0; kt < 16; kt++)
        #pragma unroll
        for (int nt = 0; nt < 4; nt++) {
            int gcol = nt * 256 + (int)r * 32 + ww * 8 + g;
            bf[kt][nt][0] = packh2(Whh[(size_t)(kt * 16 + 2 * t4) * GDIM + gcol],
                                   Whh[(size_t)(kt * 16 + 2 * t4 + 1) * GDIM + gcol]);
            bf[kt][nt][1] = packh2(Whh[(size_t)(kt * 16 + 8 + 2 * t4) * GDIM + gcol],
                                   Whh[(size_t)(kt * 16 + 8 + 2 * t4 + 1) * GDIM + gcol]);
        }
    __syncthreads();
    asm volatile("barrier.cluster.arrive.aligned;" ::: "memory");
    asm volatile("barrier.cluster.wait.aligned;" ::: "memory");

    const uint32_t laneoff = (uint32_t)((lane >> 4) * 256 + (lane & 15) * 16);
    const int hcol = ww * 8 + 2 * t4;
    const uint32_t st0 = (uint32_t)(ww * 256 + g * 16 + t4 * 4);
    const uint32_t st1 = (uint32_t)(ww * 256 + (g + 8) * 16 + t4 * 4);
    float c00 = 0.f, c01 = 0.f, c10 = 0.f, c11 = 0.f;
    int ph[2] = {0, 0};

    // single poller per group for t=0, then group barrier
    if (ltid == 0) wait_ready(0);
    bar_sync(3 + gi, 128);

    for (int t = 0; t < TSTEPS; t++) {
        const int b = t & 1, nbuf = b ^ 1;
        const float* xr = g_xpb + (size_t)t * (256 * GDIM)
                        + (size_t)(cid * 32 + gi * 16 + g) * GDIM + (int)r * 32 + hcol;
        const float* xr2 = xr + 8 * GDIM;
        float2 xi0 = __ldcg((const float2*)xr);
        float2 xf0 = __ldcg((const float2*)(xr + 256));
        float2 xg0 = __ldcg((const float2*)(xr + 512));
        float2 xo0 = __ldcg((const float2*)(xr + 768));
        float2 xi1 = __ldcg((const float2*)xr2);
        float2 xf1 = __ldcg((const float2*)(xr2 + 256));
        float2 xg1 = __ldcg((const float2*)(xr2 + 512));
        float2 xo1 = __ldcg((const float2*)(xr2 + 768));

        float acc[4][4] = {}, acc2[4][4] = {};
        if (t) {
            uint32_t mb = smem0 + MB_B + (gi * 2 + b) * 8;
            mbar_wait(mb, (uint32_t)ph[b]);
            ph[b] ^= 1;
            if (ltid == 0) mbar_expect(mb, 8192);
            uint32_t ab = smem0 + (uint32_t)AS_B(gi, b) + laneoff;
            #pragma unroll
            for (int kt = 0; kt < 8; kt++) {
                uint32_t a[4];
                ldsm4(a, ab + (uint32_t)(kt * 512));
                #pragma unroll
                for (int nt = 0; nt < 4; nt++) mma_f16(acc[nt], a, bf[kt][nt][0], bf[kt][nt][1]);
            }
            #pragma unroll
            for (int kt = 8; kt < 16; kt++) {
                uint32_t a[4];
                ldsm4(a, ab + (uint32_t)(kt * 512));
                #pragma unroll
                for (int nt = 0; nt < 4; nt++) mma_f16(acc2[nt], a, bf[kt][nt][0], bf[kt][nt][1]);
            }
        }
        float i00 = sigf(acc[0][0] + acc2[0][0] + xi0.x);
        float i01 = sigf(acc[0][1] + acc2[0][1] + xi0.y);
        float i10 = sigf(acc[0][2] + acc2[0][2] + xi1.x);
        float i11 = sigf(acc[0][3] + acc2[0][3] + xi1.y);
        float f00 = sigf(acc[1][0] + acc2[1][0] + xf0.x);
        float f01 = sigf(acc[1][1] + acc2[1][1] + xf0.y);
        float f10 = sigf(acc[1][2] + acc2[1][2] + xf1.x);
        float f11 = sigf(acc[1][3] + acc2[1][3] + xf1.y);
        float G00 = tanhf(acc[2][0] + acc2[2][0] + xg0.x);
        float G01 = tanhf(acc[2][1] + acc2[2][1] + xg0.y);
        float G10 = tanhf(acc[2][2] + acc2[2][2] + xg1.x);
        float G11 = tanhf(acc[2][3] + acc2[2][3] + xg1.y);
        float o00 = sigf(acc[3][0] + acc2[3][0] + xo0.x);
        float o01 = sigf(acc[3][1] + acc2[3][1] + xo0.y);
        float o10 = sigf(acc[3][2] + acc2[3][2] + xo1.x);
        float o11 = sigf(acc[3][3] + acc2[3][3] + xo1.y);
        c00 = f00 * c00 + i00 * G00;  c01 = f01 * c01 + i01 * G01;
        c10 = f10 * c10 + i10 * G10;  c11 = f11 * c11 + i11 * G11;
        float h00 = o00 * tanhf(c00), h01 = o01 * tanhf(c01);
        float h10 = o10 * tanhf(c10), h11 = o11 * tanhf(c11);
        *(uint32_t*)(smc + ST_B(gi) + st0) = packh2(h00, h01);
        *(uint32_t*)(smc + ST_B(gi) + st1) = packh2(h10, h11);
        bar_sync(1 + gi, 128);
        if (ltid == 0 && t < TSTEPS - 1) {
            asm volatile("fence.proxy.async.shared::cta;" ::: "memory");
            uint32_t src = smem0 + (uint32_t)ST_B(gi);
            uint32_t dstl = smem0 + (uint32_t)AS_B(gi, nbuf) + r * 1024;
            uint32_t mbl = smem0 + MB_B + (gi * 2 + nbuf) * 8;
            #pragma unroll
            for (uint32_t dr = 0; dr < 8; dr++)
                bulk_s2s(mapa_rank(dstl, dr), src, 1024u, mapa_rank(mbl, dr));
        }
        size_t row0 = (size_t)(cid * 32 + gi * 16 + g) * 256 + (int)r * 32 + hcol;
        *(float2*)(out + (size_t)t * 65536 + row0) = make_float2(h00, h01);
        *(float2*)(out + (size_t)t * 65536 + row0 + 8 * 256) = make_float2(h10, h11);
        if (tail && t == TSTEPS - 1) {
            *(float2*)(out + HSEQ + row0) = make_float2(h00, h01);
            *(float2*)(out + HSEQ + row0 + 8 * 256) = make_float2(h10, h11);
            *(float2*)(out + HSEQ + 65536 + row0) = make_float2(c00, c01);
            *(float2*)(out + HSEQ + 65536 + row0 + 8 * 256) = make_float2(c10, c11);
        }
        // single-poller readiness check for t+1, then cheap group barrier
        if (t < TSTEPS - 1) {
            if (ltid == 0) wait_ready(t + 1);
            bar_sync(3 + gi, 128);
        }
    }
    if (ltid == 0) {
        asm volatile("cp.async.bulk.commit_group;" ::: "memory");
        asm volatile("cp.async.bulk.wait_group.read 0;" ::: "memory");
    }
    __syncthreads();
    asm volatile("barrier.cluster.arrive.aligned;" ::: "memory");
    asm volatile("barrier.cluster.wait.aligned;" ::: "memory");
}

extern "C" void kernel_launch(void* const* d_in, const int* in_sizes, int n_in,
                              void* d_out, int out_size) {
    const float* x    = (const float*)d_in[0];
    const float* wih  = (const float*)d_in[1];
    const float* whh  = (const float*)d_in[2];
    const float* bias = (const float*)d_in[3];
    float* out = (float*)d_out;
    (void)in_sizes; (void)n_in;
    cudaFuncSetAttribute(fused_kernel, cudaFuncAttributeMaxDynamicSharedMemorySize, PROJ_SMEM);
    reset_kernel<<<1, TSTEPS>>>();
    int tail = ((size_t)out_size >= HSEQ + 2 * 65536) ? 1 : 0;
    fused_kernel<<<64 + 16384, 256, PROJ_SMEM>>>(x, wih, bias, whh, out, tail);
}